// round 15
// baseline (speedup 1.0000x reference)
#include <cuda_runtime.h>
#include <cuda_fp16.h>
#include <math.h>
#include <stdint.h>

// ---------------------------------------------------------------------------
// GQA: B=1, S=2048, D=128, H=32 heads, G=8 kv heads, causal, RoPE on K and V.
// fp16 mma.sync everywhere. Attention: 128 q-rows/CTA, 4 warps x 32 rows,
// kv-tile 64, Q in smem, P register-resident, 2 CTAs/SM.
// ---------------------------------------------------------------------------

constexpr size_t OFF_QH   = 0;                    // 2048x4096 fp16 -> 4M floats
constexpr size_t OFF_KH   = OFF_QH  + 4194304;    // 2048x1024 fp16 -> 1M
constexpr size_t OFF_VH   = OFF_KH  + 1048576;
constexpr size_t OFF_KF   = OFF_VH  + 1048576;    // [8][32 tiles][16KB] fp16 packed
constexpr size_t OFF_VF   = OFF_KF  + 2097152;
constexpr size_t OFF_OC   = OFF_VF  + 2097152;    // 2048x4096 fp16 -> 4M
constexpr size_t OFF_PART = OFF_OC  + 4194304;    // [16][2048][128] fp32
constexpr size_t BUF_TOTAL = OFF_PART + 4194304;

__device__ float g_buf[BUF_TOTAL];
__device__ float g_invfreq[64];

__global__ void init_invfreq() {
    int j = threadIdx.x;
    g_invfreq[j] = (float)exp(-(double)j / 64.0 * log(10000.0));
}

__device__ __forceinline__ uint32_t pack_h2(float lo, float hi) {
    uint32_t u;
    asm("cvt.rn.f16x2.f32 %0, %1, %2;" : "=r"(u) : "f"(hi), "f"(lo));
    return u;
}

__device__ __forceinline__ void mma_f16(float* c, uint32_t a0, uint32_t a1,
                                        uint32_t a2, uint32_t a3,
                                        uint32_t b0, uint32_t b1) {
    asm volatile(
        "mma.sync.aligned.m16n8k16.row.col.f32.f16.f16.f32 "
        "{%0,%1,%2,%3}, {%4,%5,%6,%7}, {%8,%9}, {%0,%1,%2,%3};"
        : "+f"(c[0]), "+f"(c[1]), "+f"(c[2]), "+f"(c[3])
        : "r"(a0), "r"(a1), "r"(a2), "r"(a3), "r"(b0), "r"(b1));
}

__device__ __forceinline__ void cp16(void* s, const void* g) {
    uint32_t sa = (uint32_t)__cvta_generic_to_shared(s);
    asm volatile("cp.async.ca.shared.global [%0], [%1], 16;" :: "r"(sa), "l"(g));
}
__device__ __forceinline__ void cp_commit() {
    asm volatile("cp.async.commit_group;" ::: "memory");
}
__device__ __forceinline__ void cp_wait0() {
    asm volatile("cp.async.wait_group 0;" ::: "memory");
}

// ---------------------------------------------------------------------------
// Fused Q/K/V projection, fp16 mma, K=128 single-shot. grid (48, 16).
// ---------------------------------------------------------------------------
__global__ void __launch_bounds__(256) gemm_qkv(
    const float* __restrict__ Xq, const float* __restrict__ Xk,
    const float* __restrict__ Xv,
    const float* __restrict__ Wq, const float* __restrict__ bq,
    const float* __restrict__ Wk, const float* __restrict__ bk,
    const float* __restrict__ Wv, const float* __restrict__ bv,
    uint32_t* __restrict__ Qh, uint32_t* __restrict__ Kh,
    uint32_t* __restrict__ Vh) {
    extern __shared__ uint32_t smE[];
    uint32_t* AsU = smE;            // 128 x 68
    uint32_t* BsU = smE + 128 * 68;

    const int bx = blockIdx.x;
    const float *A, *B, *bias;
    uint32_t* C;
    int N, n0;
    float ws;
    if (bx < 32)      { A = Xq; B = Wq; bias = bq; C = Qh; N = 4096; n0 = bx * 128;
                        ws = 0.08838834764831845f; }
    else if (bx < 40) { A = Xk; B = Wk; bias = bk; C = Kh; N = 1024; n0 = (bx - 32) * 128;
                        ws = 1.f; }
    else              { A = Xv; B = Wv; bias = bv; C = Vh; N = 1024; n0 = (bx - 40) * 128;
                        ws = 1.f; }

    const int t = threadIdx.x, lane = t & 31, wid = t >> 5;
    const int gq = lane >> 2, qd = lane & 3;
    const int m0 = blockIdx.y * 128;
    const int mw = (wid & 3) * 32, nw = (wid >> 2) * 64;

    for (int i = t; i < 4096; i += 256) {
        int r = i >> 5, c4 = (i & 31) << 2;
        float4 a = *(const float4*)&A[(size_t)(m0 + r) * 128 + c4];
        float4 b = *(const float4*)&B[(size_t)(n0 + r) * 128 + c4];
        *(uint2*)&AsU[r * 68 + (c4 >> 1)] =
            make_uint2(pack_h2(a.x, a.y), pack_h2(a.z, a.w));
        *(uint2*)&BsU[r * 68 + (c4 >> 1)] =
            make_uint2(pack_h2(b.x * ws, b.y * ws), pack_h2(b.z * ws, b.w * ws));
    }
    __syncthreads();

    float acc[2][8][4];
    #pragma unroll
    for (int s = 0; s < 2; ++s)
        #pragma unroll
        for (int j = 0; j < 8; ++j)
            #pragma unroll
            for (int c = 0; c < 4; ++c) acc[s][j][c] = 0.f;

    #pragma unroll
    for (int ks = 0; ks < 8; ++ks) {
        uint32_t a[2][4];
        #pragma unroll
        for (int s = 0; s < 2; ++s) {
            int rb = mw + s * 16;
            a[s][0] = AsU[(rb + gq) * 68 + ks * 8 + qd];
            a[s][1] = AsU[(rb + gq + 8) * 68 + ks * 8 + qd];
            a[s][2] = AsU[(rb + gq) * 68 + ks * 8 + 4 + qd];
            a[s][3] = AsU[(rb + gq + 8) * 68 + ks * 8 + 4 + qd];
        }
        #pragma unroll
        for (int j = 0; j < 8; ++j) {
            uint32_t b0 = BsU[(nw + j * 8 + gq) * 68 + ks * 8 + qd];
            uint32_t b1 = BsU[(nw + j * 8 + gq) * 68 + ks * 8 + 4 + qd];
            #pragma unroll
            for (int s = 0; s < 2; ++s)
                mma_f16(acc[s][j], a[s][0], a[s][1], a[s][2], a[s][3], b0, b1);
        }
    }

    const int NW = N >> 1;
    #pragma unroll
    for (int s = 0; s < 2; ++s) {
        int row = m0 + mw + s * 16 + gq;
        #pragma unroll
        for (int j = 0; j < 8; ++j) {
            int col = n0 + nw + j * 8 + 2 * qd;
            float b0 = bias[col] * ws, b1 = bias[col + 1] * ws;
            C[(size_t)row * NW + (col >> 1)] =
                pack_h2(acc[s][j][0] + b0, acc[s][j][1] + b1);
            C[(size_t)(row + 8) * NW + (col >> 1)] =
                pack_h2(acc[s][j][2] + b0, acc[s][j][3] + b1);
        }
    }
}

// ---------------------------------------------------------------------------
// Out-projection, fp16 mma, split-K. grid (1,16,16).
// ---------------------------------------------------------------------------
__global__ void __launch_bounds__(256) gemm_out(
    const uint32_t* __restrict__ Aw,   // Oc fp16, 2048 x 2048 u32 words
    const float* __restrict__ B,       // Wo fp32 [128][4096]
    float* __restrict__ C, int kSplit) {
    __shared__ uint32_t AsU[128 * 36];
    __shared__ uint32_t BsU[128 * 36];

    const int t = threadIdx.x, lane = t & 31, wid = t >> 5;
    const int gq = lane >> 2, qd = lane & 3;
    const int m0 = blockIdx.y * 128;
    const int mw = (wid & 3) * 32, nw = (wid >> 2) * 64;
    const int kBeg = blockIdx.z * kSplit;
    const int kEnd = kBeg + kSplit;

    float acc[2][8][4];
    #pragma unroll
    for (int s = 0; s < 2; ++s)
        #pragma unroll
        for (int j = 0; j < 8; ++j)
            #pragma unroll
            for (int c = 0; c < 4; ++c) acc[s][j][c] = 0.f;

    for (int kc = kBeg; kc < kEnd; kc += 64) {
        __syncthreads();
        for (int i = t; i < 1024; i += 256) {
            int r = i >> 3, w = (i & 7) << 2;
            *(uint4*)&AsU[r * 36 + w] =
                *(const uint4*)&Aw[(size_t)(m0 + r) * 2048 + (kc >> 1) + w];
        }
        for (int i = t; i < 2048; i += 256) {
            int r = i >> 4, c4 = (i & 15) << 2;
            float4 b = *(const float4*)&B[(size_t)r * 4096 + kc + c4];
            *(uint2*)&BsU[r * 36 + (c4 >> 1)] =
                make_uint2(pack_h2(b.x, b.y), pack_h2(b.z, b.w));
        }
        __syncthreads();
        #pragma unroll
        for (int ks = 0; ks < 4; ++ks) {
            uint32_t a[2][4];
            #pragma unroll
            for (int s = 0; s < 2; ++s) {
                int rb = mw + s * 16;
                a[s][0] = AsU[(rb + gq) * 36 + ks * 8 + qd];
                a[s][1] = AsU[(rb + gq + 8) * 36 + ks * 8 + qd];
                a[s][2] = AsU[(rb + gq) * 36 + ks * 8 + 4 + qd];
                a[s][3] = AsU[(rb + gq + 8) * 36 + ks * 8 + 4 + qd];
            }
            #pragma unroll
            for (int j = 0; j < 8; ++j) {
                uint32_t b0 = BsU[(nw + j * 8 + gq) * 36 + ks * 8 + qd];
                uint32_t b1 = BsU[(nw + j * 8 + gq) * 36 + ks * 8 + 4 + qd];
                #pragma unroll
                for (int s = 0; s < 2; ++s)
                    mma_f16(acc[s][j], a[s][0], a[s][1], a[s][2], a[s][3], b0, b1);
            }
        }
    }

    float* Cz = C + (size_t)blockIdx.z * 2048 * 128;
    #pragma unroll
    for (int s = 0; s < 2; ++s) {
        int row = m0 + mw + s * 16 + gq;
        #pragma unroll
        for (int j = 0; j < 8; ++j) {
            int col = nw + j * 8 + 2 * qd;
            *(float2*)&Cz[(size_t)row * 128 + col] =
                make_float2(acc[s][j][0], acc[s][j][1]);
            *(float2*)&Cz[(size_t)(row + 8) * 128 + col] =
                make_float2(acc[s][j][2], acc[s][j][3]);
        }
    }
}

// ---------------------------------------------------------------------------
// RoPE + fp16 fragment-quad packers (z=0 -> K, z=1 -> V). 64-kv tiles, 16KB.
// ---------------------------------------------------------------------------
__global__ void rope_pack(const __half* __restrict__ Kh, const __half* __restrict__ Vh,
                          uint4* __restrict__ Kf, uint4* __restrict__ Vf) {
    __shared__ float S[64][129];
    __shared__ float fr[64];
    int g = blockIdx.y, kb = blockIdx.x, z = blockIdx.z, t = threadIdx.x;
    if (t < 64) fr[t] = g_invfreq[t];
    __syncthreads();
    const __half* src = (z ? Vh : Kh) + (size_t)g * 262144 + (size_t)kb * 8192;
    for (int i = t; i < 4096; i += 256) {
        int r = i >> 6, d = i & 63;
        float x1 = __half2float(src[r * 128 + d]);
        float x2 = __half2float(src[r * 128 + d + 64]);
        float ang = (float)(kb * 64 + r) * fr[d];
        float sn, cs;
        sincosf(ang, &sn, &cs);
        S[r][d]      = x1 * cs - x2 * sn;
        S[r][d + 64] = x1 * sn + x2 * cs;
    }
    __syncthreads();
    if (z == 0) {
        uint4* dst = Kf + ((size_t)g * 32 + kb) * 1024;
        for (int i = t; i < 1024; i += 256) {
            int ks = i >> 7, jp = (i >> 5) & 3, l = i & 31;
            int gq = l >> 2, qd = l & 3;
            int c0 = jp * 16 + gq, d0 = ks * 16 + 2 * qd;
            dst[i] = make_uint4(
                pack_h2(S[c0][d0],     S[c0][d0 + 1]),
                pack_h2(S[c0][d0 + 8], S[c0][d0 + 9]),
                pack_h2(S[c0 + 8][d0],     S[c0 + 8][d0 + 1]),
                pack_h2(S[c0 + 8][d0 + 8], S[c0 + 8][d0 + 9]));
        }
    } else {
        uint4* dst = Vf + ((size_t)g * 32 + kb) * 1024;
        for (int i = t; i < 1024; i += 256) {
            int ks = i >> 8, jp = (i >> 5) & 7, l = i & 31;
            int gq = l >> 2, qd = l & 3;
            int k0 = ks * 16 + 2 * qd, c0 = jp * 16 + gq;
            dst[i] = make_uint4(
                pack_h2(S[k0][c0],     S[k0 + 1][c0]),
                pack_h2(S[k0 + 8][c0], S[k0 + 9][c0]),
                pack_h2(S[k0][c0 + 8],     S[k0 + 1][c0 + 8]),
                pack_h2(S[k0 + 8][c0 + 8], S[k0 + 9][c0 + 8]));
        }
    }
}

// ---------------------------------------------------------------------------
// Flash attention: 128 threads, 4 warps x 32 q-rows = 128 q-rows/CTA,
// kv-tile 64, Q in smem (A-frags re-read per tile), P register-resident,
// 2 CTAs/SM. Each B-frag LDS.128 feeds 4 MMAs (2 row-groups).
// ---------------------------------------------------------------------------
#define KV0  0          // K (4096 floats) + V (4096 floats) = 32KB
#define KV1  8192
#define QS   16384      // Q: 128 rows x 68 words = 8704 (also epilogue stage)
#define ASMF 25088      // floats -> 100352 bytes

__global__ void __launch_bounds__(128, 2) attn_mma(
    const uint4* __restrict__ Qh,     // fp16 [32][2048][128], 16 uint4/row
    const uint4* __restrict__ Kf,     // fp16 frag-quad packed
    const uint4* __restrict__ Vf,
    uint32_t* __restrict__ OcW) {     // fp16 [2048][4096] as u32 words
    extern __shared__ float sm[];
    uint32_t* smU = (uint32_t*)sm;
    uint32_t* QsU = smU + QS;

    const int t = threadIdx.x, lane = t & 31, wid = t >> 5;
    const int gq = lane >> 2, qd = lane & 3;
    const int h = blockIdx.y, g = h & 7;
    const int qb = gridDim.x - 1 - blockIdx.x;  // big blocks first
    const int s0 = qb * 128, m0 = wid * 32;

    // ---- Q (128 rows, fp16 with scale pre-folded) -> smem, stays resident
    const uint4* qsrc = Qh + ((size_t)h * 2048 + s0) * 16;
    for (int i = t; i < 2048; i += 128) {
        int r = i >> 4, w = i & 15;
        *(uint4*)&QsU[r * 68 + w * 4] = qsrc[r * 16 + w];
    }

    float l[4] = {0.f, 0.f, 0.f, 0.f};
    float o_acc[2][16][4];
    #pragma unroll
    for (int rg = 0; rg < 2; ++rg)
        #pragma unroll
        for (int j = 0; j < 16; ++j)
            #pragma unroll
            for (int c = 0; c < 4; ++c) o_acc[rg][j][c] = 0.f;

    const int ntiles = qb * 2 + 2;
    const float* kbase = (const float*)(Kf + (size_t)g * 32 * 1024);
    const float* vbase = (const float*)(Vf + (size_t)g * 32 * 1024);

    // prologue: tile 0 K+V, single group
    for (int i = t; i < 1024; i += 128) {
        cp16(&sm[KV0 + i * 4], &kbase[i * 4]);
        cp16(&sm[KV0 + 4096 + i * 4], &vbase[i * 4]);
    }
    cp_commit();
    __syncthreads();   // Q visible to all warps (each warp reads only its rows,
                       // but keep it tight before the loop)

    for (int kb = 0; kb < ntiles; ++kb) {
        cp_wait0();
        __syncthreads();
        if (kb + 1 < ntiles) {
            float* b = sm + ((kb & 1) ? KV0 : KV1);
            const float* kg = kbase + (size_t)(kb + 1) * 4096;
            const float* vg = vbase + (size_t)(kb + 1) * 4096;
            for (int i = t; i < 1024; i += 128) {
                cp16(&b[i * 4], &kg[i * 4]);
                cp16(&b[4096 + i * 4], &vg[i * 4]);
            }
            cp_commit();
        }
        const float* cur = sm + ((kb & 1) ? KV1 : KV0);
        const uint4* K4 = (const uint4*)cur;
        const uint4* V4 = (const uint4*)(cur + 4096);

        // S = Q K^T : per-warp 32 x 64; A-frags from smem, B shared by 2 groups
        float s_acc[2][8][4];
        #pragma unroll
        for (int rg = 0; rg < 2; ++rg)
            #pragma unroll
            for (int j = 0; j < 8; ++j)
                #pragma unroll
                for (int c = 0; c < 4; ++c) s_acc[rg][j][c] = 0.f;
        #pragma unroll
        for (int ks = 0; ks < 8; ++ks) {
            uint32_t a[2][4];
            #pragma unroll
            for (int rg = 0; rg < 2; ++rg) {
                int rb = (m0 + rg * 16 + gq) * 68 + ks * 8;
                a[rg][0] = QsU[rb + qd];
                a[rg][1] = QsU[rb + 8 * 68 + qd];
                a[rg][2] = QsU[rb + 4 + qd];
                a[rg][3] = QsU[rb + 8 * 68 + 4 + qd];
            }
            #pragma unroll
            for (int jp = 0; jp < 4; ++jp) {
                uint4 b = K4[ks * 128 + jp * 32 + lane];
                #pragma unroll
                for (int rg = 0; rg < 2; ++rg) {
                    mma_f16(s_acc[rg][2 * jp], a[rg][0], a[rg][1], a[rg][2],
                            a[rg][3], b.x, b.y);
                    mma_f16(s_acc[rg][2 * jp + 1], a[rg][0], a[rg][1], a[rg][2],
                            a[rg][3], b.z, b.w);
                }
            }
        }

        // softmax without max -> P fragments in registers
        const bool mt = (kb >= ntiles - 2);
        uint32_t pa[2][8][2];
        #pragma unroll
        for (int rg = 0; rg < 2; ++rg) {
            const int r0 = s0 + m0 + rg * 16 + gq;
            #pragma unroll
            for (int j = 0; j < 8; ++j) {
                float p0 = __expf(s_acc[rg][j][0]);
                float p1 = __expf(s_acc[rg][j][1]);
                float p2 = __expf(s_acc[rg][j][2]);
                float p3 = __expf(s_acc[rg][j][3]);
                if (mt) {
                    int col = kb * 64 + j * 8 + 2 * qd;
                    if (col > r0)         p0 = 0.f;
                    if (col + 1 > r0)     p1 = 0.f;
                    if (col > r0 + 8)     p2 = 0.f;
                    if (col + 1 > r0 + 8) p3 = 0.f;
                }
                l[rg * 2]     += p0 + p1;
                l[rg * 2 + 1] += p2 + p3;
                pa[rg][j][0] = pack_h2(p0, p1);
                pa[rg][j][1] = pack_h2(p2, p3);
            }
        }

        // O += P V : per-warp 32 x 128, P from registers, V shared by 2 groups
        #pragma unroll
        for (int ks = 0; ks < 4; ++ks) {
            #pragma unroll
            for (int jp = 0; jp < 8; ++jp) {
                uint4 v = V4[ks * 256 + jp * 32 + lane];
                #pragma unroll
                for (int rg = 0; rg < 2; ++rg) {
                    mma_f16(o_acc[rg][2 * jp], pa[rg][2 * ks][0], pa[rg][2 * ks][1],
                            pa[rg][2 * ks + 1][0], pa[rg][2 * ks + 1][1], v.x, v.y);
                    mma_f16(o_acc[rg][2 * jp + 1], pa[rg][2 * ks][0], pa[rg][2 * ks][1],
                            pa[rg][2 * ks + 1][0], pa[rg][2 * ks + 1][1], v.z, v.w);
                }
            }
        }
    }

    // reduce row sums over qd lanes
    #pragma unroll
    for (int i = 0; i < 4; ++i) {
        l[i] += __shfl_xor_sync(0xffffffffu, l[i], 1);
        l[i] += __shfl_xor_sync(0xffffffffu, l[i], 2);
    }
    float inv[4];
    #pragma unroll
    for (int i = 0; i < 4; ++i) inv[i] = 1.f / l[i];

    // Epilogue: stage fp16 pairs into Q region (own rows only), then store
    #pragma unroll
    for (int rg = 0; rg < 2; ++rg)
        #pragma unroll
        for (int j = 0; j < 16; ++j) {
            int w = j * 4 + qd;
            int rb = (m0 + rg * 16 + gq) * 68;
            QsU[rb + w] = pack_h2(o_acc[rg][j][0] * inv[rg * 2],
                                  o_acc[rg][j][1] * inv[rg * 2]);
            QsU[rb + 8 * 68 + w] = pack_h2(o_acc[rg][j][2] * inv[rg * 2 + 1],
                                           o_acc[rg][j][3] * inv[rg * 2 + 1]);
        }
    __syncthreads();
    for (int i = t; i < 2048; i += 128) {
        int r = i >> 4, w4 = (i & 15) << 2;
        *(uint4*)&OcW[(size_t)(s0 + r) * 2048 + h * 64 + w4] =
            *(uint4*)&QsU[r * 68 + w4];
    }
}

// ---------------------------------------------------------------------------
__global__ void reduce_bias(const float* __restrict__ P, const float* __restrict__ bo,
                            float* __restrict__ out) {
    int i = blockIdx.x * 256 + threadIdx.x;
    float v = bo[i & 127];
    #pragma unroll
    for (int z = 0; z < 16; ++z) v += P[(size_t)z * 262144 + i];
    out[i] = v;
}

// ---------------------------------------------------------------------------
extern "C" void kernel_launch(void* const* d_in, const int* in_sizes, int n_in,
                              void* d_out, int out_size) {
    const float* query  = (const float*)d_in[0];
    const float* key    = (const float*)d_in[1];
    const float* values = (const float*)d_in[2];
    const float* Wq = (const float*)d_in[4];
    const float* bq = (const float*)d_in[5];
    const float* Wk = (const float*)d_in[6];
    const float* bk = (const float*)d_in[7];
    const float* Wv = (const float*)d_in[8];
    const float* bv = (const float*)d_in[9];
    const float* Wo = (const float*)d_in[10];
    const float* bo = (const float*)d_in[11];
    float* out = (float*)d_out;

    float* buf = nullptr;
    cudaGetSymbolAddress((void**)&buf, g_buf);
    uint32_t* Qh  = (uint32_t*)(buf + OFF_QH);
    uint32_t* Kh  = (uint32_t*)(buf + OFF_KH);
    uint32_t* Vh  = (uint32_t*)(buf + OFF_VH);
    uint4*    Kf  = (uint4*)(buf + OFF_KF);
    uint4*    Vf  = (uint4*)(buf + OFF_VF);
    uint32_t* Oc  = (uint32_t*)(buf + OFF_OC);
    float*    Part = buf + OFF_PART;

    init_invfreq<<<1, 64>>>();

    cudaFuncSetAttribute(gemm_qkv, cudaFuncAttributeMaxDynamicSharedMemorySize,
                         2 * 128 * 68 * 4);
    gemm_qkv<<<dim3(48, 16), 256, 2 * 128 * 68 * 4>>>(
        query, key, values, Wq, bq, Wk, bk, Wv, bv, Qh, Kh, Vh);

    rope_pack<<<dim3(32, 8, 2), 256>>>((const __half*)Kh, (const __half*)Vh, Kf, Vf);

    cudaFuncSetAttribute(attn_mma, cudaFuncAttributeMaxDynamicSharedMemorySize,
                         ASMF * 4);
    attn_mma<<<dim3(16, 32), 128, ASMF * 4>>>((const uint4*)Qh, Kf, Vf, Oc);

    gemm_out<<<dim3(1, 16, 16), 256>>>(Oc, Wo, Part, 256);
    reduce_bias<<<1024, 256>>>(Part, bo, out);
}

// round 16
// speedup vs baseline: 1.2000x; 1.2000x over previous
#include <cuda_runtime.h>
#include <cuda_fp16.h>
#include <math.h>
#include <stdint.h>

// ---------------------------------------------------------------------------
// GQA: B=1, S=2048, D=128, H=32 heads, G=8 kv heads, causal, RoPE on K and V.
// fp16 mma.sync everywhere. Attention = R14 config (4 warps x 16 rows,
// kv-tile 64, P register-resident, 3 CTAs/SM). Wo pre-converted to fp16.
// ---------------------------------------------------------------------------

constexpr size_t OFF_QH   = 0;                    // 2048x4096 fp16 -> 4M floats
constexpr size_t OFF_KH   = OFF_QH  + 4194304;    // 2048x1024 fp16 -> 1M
constexpr size_t OFF_VH   = OFF_KH  + 1048576;
constexpr size_t OFF_KF   = OFF_VH  + 1048576;    // [8][32 tiles][16KB] fp16 packed
constexpr size_t OFF_VF   = OFF_KF  + 2097152;
constexpr size_t OFF_OC   = OFF_VF  + 2097152;    // 2048x4096 fp16 -> 4M
constexpr size_t OFF_WOH  = OFF_OC  + 4194304;    // 128x4096 fp16 -> 256K floats
constexpr size_t OFF_PART = OFF_WOH + 262144;     // [8][2048][128] fp32
constexpr size_t BUF_TOTAL = OFF_PART + 2097152;

__device__ float g_buf[BUF_TOTAL];
__device__ float g_invfreq[64];

__global__ void init_invfreq() {
    int j = threadIdx.x;
    g_invfreq[j] = (float)exp(-(double)j / 64.0 * log(10000.0));
}

__device__ __forceinline__ uint32_t pack_h2(float lo, float hi) {
    uint32_t u;
    asm("cvt.rn.f16x2.f32 %0, %1, %2;" : "=r"(u) : "f"(hi), "f"(lo));
    return u;
}

__device__ __forceinline__ void mma_f16(float* c, uint32_t a0, uint32_t a1,
                                        uint32_t a2, uint32_t a3,
                                        uint32_t b0, uint32_t b1) {
    asm volatile(
        "mma.sync.aligned.m16n8k16.row.col.f32.f16.f16.f32 "
        "{%0,%1,%2,%3}, {%4,%5,%6,%7}, {%8,%9}, {%0,%1,%2,%3};"
        : "+f"(c[0]), "+f"(c[1]), "+f"(c[2]), "+f"(c[3])
        : "r"(a0), "r"(a1), "r"(a2), "r"(a3), "r"(b0), "r"(b1));
}

__device__ __forceinline__ void cp16(void* s, const void* g) {
    uint32_t sa = (uint32_t)__cvta_generic_to_shared(s);
    asm volatile("cp.async.ca.shared.global [%0], [%1], 16;" :: "r"(sa), "l"(g));
}
__device__ __forceinline__ void cp_commit() {
    asm volatile("cp.async.commit_group;" ::: "memory");
}
__device__ __forceinline__ void cp_wait0() {
    asm volatile("cp.async.wait_group 0;" ::: "memory");
}

// ---------------------------------------------------------------------------
// Wo fp32 -> fp16 (done once; rounding identical to per-use conversion)
// ---------------------------------------------------------------------------
__global__ void wo_convert(const float* __restrict__ Wo, uint32_t* __restrict__ Woh) {
    int i = blockIdx.x * 256 + threadIdx.x;   // 262144 words
    float2 v = *(const float2*)&Wo[(size_t)i * 2];
    Woh[i] = pack_h2(v.x, v.y);
}

// ---------------------------------------------------------------------------
// Fused Q/K/V projection, fp16 mma, K=128 single-shot. grid (48, 16).
// ---------------------------------------------------------------------------
__global__ void __launch_bounds__(256) gemm_qkv(
    const float* __restrict__ Xq, const float* __restrict__ Xk,
    const float* __restrict__ Xv,
    const float* __restrict__ Wq, const float* __restrict__ bq,
    const float* __restrict__ Wk, const float* __restrict__ bk,
    const float* __restrict__ Wv, const float* __restrict__ bv,
    uint32_t* __restrict__ Qh, uint32_t* __restrict__ Kh,
    uint32_t* __restrict__ Vh) {
    extern __shared__ uint32_t smE[];
    uint32_t* AsU = smE;            // 128 x 68
    uint32_t* BsU = smE + 128 * 68;

    const int bx = blockIdx.x;
    const float *A, *B, *bias;
    uint32_t* C;
    int N, n0;
    float ws;
    if (bx < 32)      { A = Xq; B = Wq; bias = bq; C = Qh; N = 4096; n0 = bx * 128;
                        ws = 0.08838834764831845f; }
    else if (bx < 40) { A = Xk; B = Wk; bias = bk; C = Kh; N = 1024; n0 = (bx - 32) * 128;
                        ws = 1.f; }
    else              { A = Xv; B = Wv; bias = bv; C = Vh; N = 1024; n0 = (bx - 40) * 128;
                        ws = 1.f; }

    const int t = threadIdx.x, lane = t & 31, wid = t >> 5;
    const int gq = lane >> 2, qd = lane & 3;
    const int m0 = blockIdx.y * 128;
    const int mw = (wid & 3) * 32, nw = (wid >> 2) * 64;

    for (int i = t; i < 4096; i += 256) {
        int r = i >> 5, c4 = (i & 31) << 2;
        float4 a = *(const float4*)&A[(size_t)(m0 + r) * 128 + c4];
        float4 b = *(const float4*)&B[(size_t)(n0 + r) * 128 + c4];
        *(uint2*)&AsU[r * 68 + (c4 >> 1)] =
            make_uint2(pack_h2(a.x, a.y), pack_h2(a.z, a.w));
        *(uint2*)&BsU[r * 68 + (c4 >> 1)] =
            make_uint2(pack_h2(b.x * ws, b.y * ws), pack_h2(b.z * ws, b.w * ws));
    }
    __syncthreads();

    float acc[2][8][4];
    #pragma unroll
    for (int s = 0; s < 2; ++s)
        #pragma unroll
        for (int j = 0; j < 8; ++j)
            #pragma unroll
            for (int c = 0; c < 4; ++c) acc[s][j][c] = 0.f;

    #pragma unroll
    for (int ks = 0; ks < 8; ++ks) {
        uint32_t a[2][4];
        #pragma unroll
        for (int s = 0; s < 2; ++s) {
            int rb = mw + s * 16;
            a[s][0] = AsU[(rb + gq) * 68 + ks * 8 + qd];
            a[s][1] = AsU[(rb + gq + 8) * 68 + ks * 8 + qd];
            a[s][2] = AsU[(rb + gq) * 68 + ks * 8 + 4 + qd];
            a[s][3] = AsU[(rb + gq + 8) * 68 + ks * 8 + 4 + qd];
        }
        #pragma unroll
        for (int j = 0; j < 8; ++j) {
            uint32_t b0 = BsU[(nw + j * 8 + gq) * 68 + ks * 8 + qd];
            uint32_t b1 = BsU[(nw + j * 8 + gq) * 68 + ks * 8 + 4 + qd];
            #pragma unroll
            for (int s = 0; s < 2; ++s)
                mma_f16(acc[s][j], a[s][0], a[s][1], a[s][2], a[s][3], b0, b1);
        }
    }

    const int NW = N >> 1;
    #pragma unroll
    for (int s = 0; s < 2; ++s) {
        int row = m0 + mw + s * 16 + gq;
        #pragma unroll
        for (int j = 0; j < 8; ++j) {
            int col = n0 + nw + j * 8 + 2 * qd;
            float b0 = bias[col] * ws, b1 = bias[col + 1] * ws;
            C[(size_t)row * NW + (col >> 1)] =
                pack_h2(acc[s][j][0] + b0, acc[s][j][1] + b1);
            C[(size_t)(row + 8) * NW + (col >> 1)] =
                pack_h2(acc[s][j][2] + b0, acc[s][j][3] + b1);
        }
    }
}

// ---------------------------------------------------------------------------
// Out-projection, fp16 mma, split-K=8: Part[z] = Oc(fp16) @ Woh^T. grid (1,16,8).
// ---------------------------------------------------------------------------
__global__ void __launch_bounds__(256) gemm_out(
    const uint32_t* __restrict__ Aw,   // Oc fp16, 2048 x 2048 u32 words
    const uint32_t* __restrict__ Bw,   // Woh fp16 [128][4096] -> 128 x 2048 words
    float* __restrict__ C, int kSplit) {
    __shared__ uint32_t AsU[128 * 36];
    __shared__ uint32_t BsU[128 * 36];

    const int t = threadIdx.x, lane = t & 31, wid = t >> 5;
    const int gq = lane >> 2, qd = lane & 3;
    const int m0 = blockIdx.y * 128;
    const int mw = (wid & 3) * 32, nw = (wid >> 2) * 64;
    const int kBeg = blockIdx.z * kSplit;
    const int kEnd = kBeg + kSplit;

    float acc[2][8][4];
    #pragma unroll
    for (int s = 0; s < 2; ++s)
        #pragma unroll
        for (int j = 0; j < 8; ++j)
            #pragma unroll
            for (int c = 0; c < 4; ++c) acc[s][j][c] = 0.f;

    for (int kc = kBeg; kc < kEnd; kc += 64) {
        __syncthreads();
        for (int i = t; i < 1024; i += 256) {
            int r = i >> 3, w = (i & 7) << 2;
            *(uint4*)&AsU[r * 36 + w] =
                *(const uint4*)&Aw[(size_t)(m0 + r) * 2048 + (kc >> 1) + w];
            *(uint4*)&BsU[r * 36 + w] =
                *(const uint4*)&Bw[(size_t)r * 2048 + (kc >> 1) + w];
        }
        __syncthreads();
        #pragma unroll
        for (int ks = 0; ks < 4; ++ks) {
            uint32_t a[2][4];
            #pragma unroll
            for (int s = 0; s < 2; ++s) {
                int rb = mw + s * 16;
                a[s][0] = AsU[(rb + gq) * 36 + ks * 8 + qd];
                a[s][1] = AsU[(rb + gq + 8) * 36 + ks * 8 + qd];
                a[s][2] = AsU[(rb + gq) * 36 + ks * 8 + 4 + qd];
                a[s][3] = AsU[(rb + gq + 8) * 36 + ks * 8 + 4 + qd];
            }
            #pragma unroll
            for (int j = 0; j < 8; ++j) {
                uint32_t b0 = BsU[(nw + j * 8 + gq) * 36 + ks * 8 + qd];
                uint32_t b1 = BsU[(nw + j * 8 + gq) * 36 + ks * 8 + 4 + qd];
                #pragma unroll
                for (int s = 0; s < 2; ++s)
                    mma_f16(acc[s][j], a[s][0], a[s][1], a[s][2], a[s][3], b0, b1);
            }
        }
    }

    float* Cz = C + (size_t)blockIdx.z * 2048 * 128;
    #pragma unroll
    for (int s = 0; s < 2; ++s) {
        int row = m0 + mw + s * 16 + gq;
        #pragma unroll
        for (int j = 0; j < 8; ++j) {
            int col = nw + j * 8 + 2 * qd;
            *(float2*)&Cz[(size_t)row * 128 + col] =
                make_float2(acc[s][j][0], acc[s][j][1]);
            *(float2*)&Cz[(size_t)(row + 8) * 128 + col] =
                make_float2(acc[s][j][2], acc[s][j][3]);
        }
    }
}

// ---------------------------------------------------------------------------
// RoPE + fp16 fragment-quad packers (z=0 -> K, z=1 -> V). 64-kv tiles, 16KB.
// ---------------------------------------------------------------------------
__global__ void rope_pack(const __half* __restrict__ Kh, const __half* __restrict__ Vh,
                          uint4* __restrict__ Kf, uint4* __restrict__ Vf) {
    __shared__ float S[64][129];
    __shared__ float fr[64];
    int g = blockIdx.y, kb = blockIdx.x, z = blockIdx.z, t = threadIdx.x;
    if (t < 64) fr[t] = g_invfreq[t];
    __syncthreads();
    const __half* src = (z ? Vh : Kh) + (size_t)g * 262144 + (size_t)kb * 8192;
    for (int i = t; i < 4096; i += 256) {
        int r = i >> 6, d = i & 63;
        float x1 = __half2float(src[r * 128 + d]);
        float x2 = __half2float(src[r * 128 + d + 64]);
        float ang = (float)(kb * 64 + r) * fr[d];
        float sn, cs;
        sincosf(ang, &sn, &cs);
        S[r][d]      = x1 * cs - x2 * sn;
        S[r][d + 64] = x1 * sn + x2 * cs;
    }
    __syncthreads();
    if (z == 0) {
        uint4* dst = Kf + ((size_t)g * 32 + kb) * 1024;
        for (int i = t; i < 1024; i += 256) {
            int ks = i >> 7, jp = (i >> 5) & 3, l = i & 31;
            int gq = l >> 2, qd = l & 3;
            int c0 = jp * 16 + gq, d0 = ks * 16 + 2 * qd;
            dst[i] = make_uint4(
                pack_h2(S[c0][d0],     S[c0][d0 + 1]),
                pack_h2(S[c0][d0 + 8], S[c0][d0 + 9]),
                pack_h2(S[c0 + 8][d0],     S[c0 + 8][d0 + 1]),
                pack_h2(S[c0 + 8][d0 + 8], S[c0 + 8][d0 + 9]));
        }
    } else {
        uint4* dst = Vf + ((size_t)g * 32 + kb) * 1024;
        for (int i = t; i < 1024; i += 256) {
            int ks = i >> 8, jp = (i >> 5) & 7, l = i & 31;
            int gq = l >> 2, qd = l & 3;
            int k0 = ks * 16 + 2 * qd, c0 = jp * 16 + gq;
            dst[i] = make_uint4(
                pack_h2(S[k0][c0],     S[k0 + 1][c0]),
                pack_h2(S[k0 + 8][c0], S[k0 + 9][c0]),
                pack_h2(S[k0][c0 + 8],     S[k0 + 1][c0 + 8]),
                pack_h2(S[k0 + 8][c0 + 8], S[k0 + 9][c0 + 8]));
        }
    }
}

// ---------------------------------------------------------------------------
// Flash attention (R14 config): 128 threads, 4 warps x 16 rows = 64 q-rows,
// kv-tile 64, fp16 mma, no running max, P register-resident, 3 CTAs/SM.
// ---------------------------------------------------------------------------
#define KV0  0          // K (4096 floats) + V (4096 floats) = 32KB
#define KV1  8192
#define ASMF 16384      // floats -> 65536 bytes

__global__ void __launch_bounds__(128, 3) attn_mma(
    const uint4* __restrict__ Qh,     // fp16 [32][2048][128], 16 uint4/row
    const uint4* __restrict__ Kf,     // fp16 frag-quad packed
    const uint4* __restrict__ Vf,
    uint32_t* __restrict__ OcW) {     // fp16 [2048][4096] as u32 words
    extern __shared__ float sm[];
    uint32_t* smU = (uint32_t*)sm;

    const int t = threadIdx.x, lane = t & 31, wid = t >> 5;
    const int gq = lane >> 2, qd = lane & 3;
    const int bid = blockIdx.x;
    const int qb = 31 - (bid >> 5);   // big blocks first
    const int h = bid & 31, g = h & 7;
    const int s0 = qb * 64, m0 = wid * 16;

    // ---- Q (64 rows, fp16, scale pre-folded): raw uint4 copies, 16/row
    const uint4* qsrc = Qh + ((size_t)h * 2048 + s0) * 16;
    for (int i = t; i < 1024; i += 128) {
        int r = i >> 4, w = i & 15;
        *(uint4*)&smU[r * 68 + w * 4] = qsrc[r * 16 + w];
    }
    __syncthreads();
    uint32_t qa[8][4];
    #pragma unroll
    for (int ks = 0; ks < 8; ++ks) {
        qa[ks][0] = smU[(m0 + gq) * 68 + ks * 8 + qd];
        qa[ks][1] = smU[(m0 + gq + 8) * 68 + ks * 8 + qd];
        qa[ks][2] = smU[(m0 + gq) * 68 + ks * 8 + 4 + qd];
        qa[ks][3] = smU[(m0 + gq + 8) * 68 + ks * 8 + 4 + qd];
    }
    __syncthreads();

    float l0 = 0.f, l1 = 0.f;
    float o_acc[16][4];
    #pragma unroll
    for (int j = 0; j < 16; ++j)
        #pragma unroll
        for (int c = 0; c < 4; ++c) o_acc[j][c] = 0.f;

    const int ntiles = qb + 1;
    const float* kbase = (const float*)(Kf + (size_t)g * 32 * 1024);
    const float* vbase = (const float*)(Vf + (size_t)g * 32 * 1024);

    for (int i = t; i < 1024; i += 128) {
        cp16(&sm[KV0 + i * 4], &kbase[i * 4]);
        cp16(&sm[KV0 + 4096 + i * 4], &vbase[i * 4]);
    }
    cp_commit();

    for (int kb = 0; kb < ntiles; ++kb) {
        cp_wait0();
        __syncthreads();
        if (kb + 1 < ntiles) {
            float* b = sm + ((kb & 1) ? KV0 : KV1);
            const float* kg = kbase + (size_t)(kb + 1) * 4096;
            const float* vg = vbase + (size_t)(kb + 1) * 4096;
            for (int i = t; i < 1024; i += 128) {
                cp16(&b[i * 4], &kg[i * 4]);
                cp16(&b[4096 + i * 4], &vg[i * 4]);
            }
            cp_commit();
        }
        const float* cur = sm + ((kb & 1) ? KV1 : KV0);
        const uint4* K4 = (const uint4*)cur;
        const uint4* V4 = (const uint4*)(cur + 4096);

        float s_acc[8][4];
        #pragma unroll
        for (int j = 0; j < 8; ++j)
            #pragma unroll
            for (int c = 0; c < 4; ++c) s_acc[j][c] = 0.f;
        #pragma unroll
        for (int ks = 0; ks < 8; ++ks) {
            #pragma unroll
            for (int jp = 0; jp < 4; ++jp) {
                uint4 b = K4[ks * 128 + jp * 32 + lane];
                mma_f16(s_acc[2 * jp], qa[ks][0], qa[ks][1], qa[ks][2], qa[ks][3],
                        b.x, b.y);
                mma_f16(s_acc[2 * jp + 1], qa[ks][0], qa[ks][1], qa[ks][2], qa[ks][3],
                        b.z, b.w);
            }
        }

        const bool mt = (kb == ntiles - 1);
        const int r0 = s0 + m0 + gq;
        uint32_t pa[8][2];
        #pragma unroll
        for (int j = 0; j < 8; ++j) {
            float p0 = __expf(s_acc[j][0]);
            float p1 = __expf(s_acc[j][1]);
            float p2 = __expf(s_acc[j][2]);
            float p3 = __expf(s_acc[j][3]);
            if (mt) {
                int col = kb * 64 + j * 8 + 2 * qd;
                if (col > r0)         p0 = 0.f;
                if (col + 1 > r0)     p1 = 0.f;
                if (col > r0 + 8)     p2 = 0.f;
                if (col + 1 > r0 + 8) p3 = 0.f;
            }
            l0 += p0 + p1;
            l1 += p2 + p3;
            pa[j][0] = pack_h2(p0, p1);
            pa[j][1] = pack_h2(p2, p3);
        }

        #pragma unroll
        for (int ks = 0; ks < 4; ++ks) {
            uint32_t a0 = pa[2 * ks][0],     a1 = pa[2 * ks][1];
            uint32_t a2 = pa[2 * ks + 1][0], a3 = pa[2 * ks + 1][1];
            #pragma unroll
            for (int jp = 0; jp < 8; ++jp) {
                uint4 v = V4[ks * 256 + jp * 32 + lane];
                mma_f16(o_acc[2 * jp], a0, a1, a2, a3, v.x, v.y);
                mma_f16(o_acc[2 * jp + 1], a0, a1, a2, a3, v.z, v.w);
            }
        }
    }

    l0 += __shfl_xor_sync(0xffffffffu, l0, 1);
    l0 += __shfl_xor_sync(0xffffffffu, l0, 2);
    l1 += __shfl_xor_sync(0xffffffffu, l1, 1);
    l1 += __shfl_xor_sync(0xffffffffu, l1, 2);
    float inv0 = 1.f / l0, inv1 = 1.f / l1;

    __syncthreads();
    #pragma unroll
    for (int j = 0; j < 16; ++j) {
        int w = j * 4 + qd;
        smU[(m0 + gq) * 68 + w]     = pack_h2(o_acc[j][0] * inv0, o_acc[j][1] * inv0);
        smU[(m0 + gq + 8) * 68 + w] = pack_h2(o_acc[j][2] * inv1, o_acc[j][3] * inv1);
    }
    __syncthreads();
    for (int i = t; i < 1024; i += 128) {
        int r = i >> 4, w4 = (i & 15) << 2;
        *(uint4*)&OcW[(size_t)(s0 + r) * 2048 + h * 64 + w4] =
            *(uint4*)&smU[r * 68 + w4];
    }
}

// ---------------------------------------------------------------------------
__global__ void reduce_bias(const float* __restrict__ P, const float* __restrict__ bo,
                            float* __restrict__ out) {
    int i = blockIdx.x * 256 + threadIdx.x;  // 262144 total
    float v = bo[i & 127];
    #pragma unroll
    for (int z = 0; z < 8; ++z) v += P[(size_t)z * 262144 + i];
    out[i] = v;
}

// ---------------------------------------------------------------------------
extern "C" void kernel_launch(void* const* d_in, const int* in_sizes, int n_in,
                              void* d_out, int out_size) {
    const float* query  = (const float*)d_in[0];
    const float* key    = (const float*)d_in[1];
    const float* values = (const float*)d_in[2];
    const float* Wq = (const float*)d_in[4];
    const float* bq = (const float*)d_in[5];
    const float* Wk = (const float*)d_in[6];
    const float* bk = (const float*)d_in[7];
    const float* Wv = (const float*)d_in[8];
    const float* bv = (const float*)d_in[9];
    const float* Wo = (const float*)d_in[10];
    const float* bo = (const float*)d_in[11];
    float* out = (float*)d_out;

    float* buf = nullptr;
    cudaGetSymbolAddress((void**)&buf, g_buf);
    uint32_t* Qh  = (uint32_t*)(buf + OFF_QH);
    uint32_t* Kh  = (uint32_t*)(buf + OFF_KH);
    uint32_t* Vh  = (uint32_t*)(buf + OFF_VH);
    uint4*    Kf  = (uint4*)(buf + OFF_KF);
    uint4*    Vf  = (uint4*)(buf + OFF_VF);
    uint32_t* Oc  = (uint32_t*)(buf + OFF_OC);
    uint32_t* Woh = (uint32_t*)(buf + OFF_WOH);
    float*    Part = buf + OFF_PART;

    init_invfreq<<<1, 64>>>();
    wo_convert<<<1024, 256>>>(Wo, Woh);

    cudaFuncSetAttribute(gemm_qkv, cudaFuncAttributeMaxDynamicSharedMemorySize,
                         2 * 128 * 68 * 4);
    gemm_qkv<<<dim3(48, 16), 256, 2 * 128 * 68 * 4>>>(
        query, key, values, Wq, bq, Wk, bk, Wv, bv, Qh, Kh, Vh);

    rope_pack<<<dim3(32, 8, 2), 256>>>((const __half*)Kh, (const __half*)Vh, Kf, Vf);

    cudaFuncSetAttribute(attn_mma, cudaFuncAttributeMaxDynamicSharedMemorySize,
                         ASMF * 4);
    attn_mma<<<1024, 128, ASMF * 4>>>((const uint4*)Qh, Kf, Vf, Oc);

    gemm_out<<<dim3(1, 16, 8), 256>>>(Oc, Woh, Part, 512);
    reduce_bias<<<1024, 256>>>(Part, bo, out);
}

// round 17
// speedup vs baseline: 1.2225x; 1.0187x over previous
#include <cuda_runtime.h>
#include <cuda_fp16.h>
#include <math.h>
#include <stdint.h>

// ---------------------------------------------------------------------------
// GQA: B=1, S=2048, D=128, H=32 heads, G=8 kv heads, causal, RoPE on K and V.
// fp16 mma.sync everywhere. Attention = R14 config (4 warps x 16 rows,
// kv-tile 64, P register-resident, 3 CTAs/SM). Wo fp16 pre-converted;
// RoPE cos/sin precomputed into a table (rope_pack = pure data movement).
// ---------------------------------------------------------------------------

constexpr size_t OFF_QH   = 0;                    // 2048x4096 fp16 -> 4M floats
constexpr size_t OFF_KH   = OFF_QH  + 4194304;    // 2048x1024 fp16 -> 1M
constexpr size_t OFF_VH   = OFF_KH  + 1048576;
constexpr size_t OFF_KF   = OFF_VH  + 1048576;    // [8][32 tiles][16KB] fp16 packed
constexpr size_t OFF_VF   = OFF_KF  + 2097152;
constexpr size_t OFF_OC   = OFF_VF  + 2097152;    // 2048x4096 fp16 -> 4M
constexpr size_t OFF_WOH  = OFF_OC  + 4194304;    // 128x4096 fp16 -> 256K floats
constexpr size_t OFF_PART = OFF_WOH + 262144;     // [16][2048][128] fp32
constexpr size_t BUF_TOTAL = OFF_PART + 4194304;

__device__ float g_buf[BUF_TOTAL];
__device__ float g_invfreq[64];
__device__ float2 g_sctab[131072];   // [pos][j] -> (cos, sin)

__global__ void init_invfreq() {
    int j = threadIdx.x;
    g_invfreq[j] = (float)exp(-(double)j / 64.0 * log(10000.0));
}

__global__ void init_sincos() {
    int i = blockIdx.x * 256 + threadIdx.x;   // 131072
    int pos = i >> 6, j = i & 63;
    float sn, cs;
    sincosf((float)pos * g_invfreq[j], &sn, &cs);
    g_sctab[i] = make_float2(cs, sn);
}

__device__ __forceinline__ uint32_t pack_h2(float lo, float hi) {
    uint32_t u;
    asm("cvt.rn.f16x2.f32 %0, %1, %2;" : "=r"(u) : "f"(hi), "f"(lo));
    return u;
}

__device__ __forceinline__ void mma_f16(float* c, uint32_t a0, uint32_t a1,
                                        uint32_t a2, uint32_t a3,
                                        uint32_t b0, uint32_t b1) {
    asm volatile(
        "mma.sync.aligned.m16n8k16.row.col.f32.f16.f16.f32 "
        "{%0,%1,%2,%3}, {%4,%5,%6,%7}, {%8,%9}, {%0,%1,%2,%3};"
        : "+f"(c[0]), "+f"(c[1]), "+f"(c[2]), "+f"(c[3])
        : "r"(a0), "r"(a1), "r"(a2), "r"(a3), "r"(b0), "r"(b1));
}

__device__ __forceinline__ void cp16(void* s, const void* g) {
    uint32_t sa = (uint32_t)__cvta_generic_to_shared(s);
    asm volatile("cp.async.ca.shared.global [%0], [%1], 16;" :: "r"(sa), "l"(g));
}
__device__ __forceinline__ void cp_commit() {
    asm volatile("cp.async.commit_group;" ::: "memory");
}
__device__ __forceinline__ void cp_wait0() {
    asm volatile("cp.async.wait_group 0;" ::: "memory");
}

// ---------------------------------------------------------------------------
// Wo fp32 -> fp16 (once)
// ---------------------------------------------------------------------------
__global__ void wo_convert(const float* __restrict__ Wo, uint32_t* __restrict__ Woh) {
    int i = blockIdx.x * 256 + threadIdx.x;   // 262144 words
    float2 v = *(const float2*)&Wo[(size_t)i * 2];
    Woh[i] = pack_h2(v.x, v.y);
}

// ---------------------------------------------------------------------------
// Fused Q/K/V projection, fp16 mma, K=128 single-shot. grid (48, 16).
// ---------------------------------------------------------------------------
__global__ void __launch_bounds__(256) gemm_qkv(
    const float* __restrict__ Xq, const float* __restrict__ Xk,
    const float* __restrict__ Xv,
    const float* __restrict__ Wq, const float* __restrict__ bq,
    const float* __restrict__ Wk, const float* __restrict__ bk,
    const float* __restrict__ Wv, const float* __restrict__ bv,
    uint32_t* __restrict__ Qh, uint32_t* __restrict__ Kh,
    uint32_t* __restrict__ Vh) {
    extern __shared__ uint32_t smE[];
    uint32_t* AsU = smE;            // 128 x 68
    uint32_t* BsU = smE + 128 * 68;

    const int bx = blockIdx.x;
    const float *A, *B, *bias;
    uint32_t* C;
    int N, n0;
    float ws;
    if (bx < 32)      { A = Xq; B = Wq; bias = bq; C = Qh; N = 4096; n0 = bx * 128;
                        ws = 0.08838834764831845f; }
    else if (bx < 40) { A = Xk; B = Wk; bias = bk; C = Kh; N = 1024; n0 = (bx - 32) * 128;
                        ws = 1.f; }
    else              { A = Xv; B = Wv; bias = bv; C = Vh; N = 1024; n0 = (bx - 40) * 128;
                        ws = 1.f; }

    const int t = threadIdx.x, lane = t & 31, wid = t >> 5;
    const int gq = lane >> 2, qd = lane & 3;
    const int m0 = blockIdx.y * 128;
    const int mw = (wid & 3) * 32, nw = (wid >> 2) * 64;

    for (int i = t; i < 4096; i += 256) {
        int r = i >> 5, c4 = (i & 31) << 2;
        float4 a = *(const float4*)&A[(size_t)(m0 + r) * 128 + c4];
        float4 b = *(const float4*)&B[(size_t)(n0 + r) * 128 + c4];
        *(uint2*)&AsU[r * 68 + (c4 >> 1)] =
            make_uint2(pack_h2(a.x, a.y), pack_h2(a.z, a.w));
        *(uint2*)&BsU[r * 68 + (c4 >> 1)] =
            make_uint2(pack_h2(b.x * ws, b.y * ws), pack_h2(b.z * ws, b.w * ws));
    }
    __syncthreads();

    float acc[2][8][4];
    #pragma unroll
    for (int s = 0; s < 2; ++s)
        #pragma unroll
        for (int j = 0; j < 8; ++j)
            #pragma unroll
            for (int c = 0; c < 4; ++c) acc[s][j][c] = 0.f;

    #pragma unroll
    for (int ks = 0; ks < 8; ++ks) {
        uint32_t a[2][4];
        #pragma unroll
        for (int s = 0; s < 2; ++s) {
            int rb = mw + s * 16;
            a[s][0] = AsU[(rb + gq) * 68 + ks * 8 + qd];
            a[s][1] = AsU[(rb + gq + 8) * 68 + ks * 8 + qd];
            a[s][2] = AsU[(rb + gq) * 68 + ks * 8 + 4 + qd];
            a[s][3] = AsU[(rb + gq + 8) * 68 + ks * 8 + 4 + qd];
        }
        #pragma unroll
        for (int j = 0; j < 8; ++j) {
            uint32_t b0 = BsU[(nw + j * 8 + gq) * 68 + ks * 8 + qd];
            uint32_t b1 = BsU[(nw + j * 8 + gq) * 68 + ks * 8 + 4 + qd];
            #pragma unroll
            for (int s = 0; s < 2; ++s)
                mma_f16(acc[s][j], a[s][0], a[s][1], a[s][2], a[s][3], b0, b1);
        }
    }

    const int NW = N >> 1;
    #pragma unroll
    for (int s = 0; s < 2; ++s) {
        int row = m0 + mw + s * 16 + gq;
        #pragma unroll
        for (int j = 0; j < 8; ++j) {
            int col = n0 + nw + j * 8 + 2 * qd;
            float b0 = bias[col] * ws, b1 = bias[col + 1] * ws;
            C[(size_t)row * NW + (col >> 1)] =
                pack_h2(acc[s][j][0] + b0, acc[s][j][1] + b1);
            C[(size_t)(row + 8) * NW + (col >> 1)] =
                pack_h2(acc[s][j][2] + b0, acc[s][j][3] + b1);
        }
    }
}

// ---------------------------------------------------------------------------
// Out-projection, fp16 mma, split-K=16: Part[z] = Oc(fp16) @ Woh^T. grid (1,16,16).
// ---------------------------------------------------------------------------
__global__ void __launch_bounds__(256) gemm_out(
    const uint32_t* __restrict__ Aw,   // Oc fp16, 2048 x 2048 u32 words
    const uint32_t* __restrict__ Bw,   // Woh fp16, 128 x 2048 words
    float* __restrict__ C, int kSplit) {
    __shared__ uint32_t AsU[128 * 36];
    __shared__ uint32_t BsU[128 * 36];

    const int t = threadIdx.x, lane = t & 31, wid = t >> 5;
    const int gq = lane >> 2, qd = lane & 3;
    const int m0 = blockIdx.y * 128;
    const int mw = (wid & 3) * 32, nw = (wid >> 2) * 64;
    const int kBeg = blockIdx.z * kSplit;
    const int kEnd = kBeg + kSplit;

    float acc[2][8][4];
    #pragma unroll
    for (int s = 0; s < 2; ++s)
        #pragma unroll
        for (int j = 0; j < 8; ++j)
            #pragma unroll
            for (int c = 0; c < 4; ++c) acc[s][j][c] = 0.f;

    for (int kc = kBeg; kc < kEnd; kc += 64) {
        __syncthreads();
        for (int i = t; i < 1024; i += 256) {
            int r = i >> 3, w = (i & 7) << 2;
            *(uint4*)&AsU[r * 36 + w] =
                *(const uint4*)&Aw[(size_t)(m0 + r) * 2048 + (kc >> 1) + w];
            *(uint4*)&BsU[r * 36 + w] =
                *(const uint4*)&Bw[(size_t)r * 2048 + (kc >> 1) + w];
        }
        __syncthreads();
        #pragma unroll
        for (int ks = 0; ks < 4; ++ks) {
            uint32_t a[2][4];
            #pragma unroll
            for (int s = 0; s < 2; ++s) {
                int rb = mw + s * 16;
                a[s][0] = AsU[(rb + gq) * 36 + ks * 8 + qd];
                a[s][1] = AsU[(rb + gq + 8) * 36 + ks * 8 + qd];
                a[s][2] = AsU[(rb + gq) * 36 + ks * 8 + 4 + qd];
                a[s][3] = AsU[(rb + gq + 8) * 36 + ks * 8 + 4 + qd];
            }
            #pragma unroll
            for (int j = 0; j < 8; ++j) {
                uint32_t b0 = BsU[(nw + j * 8 + gq) * 36 + ks * 8 + qd];
                uint32_t b1 = BsU[(nw + j * 8 + gq) * 36 + ks * 8 + 4 + qd];
                #pragma unroll
                for (int s = 0; s < 2; ++s)
                    mma_f16(acc[s][j], a[s][0], a[s][1], a[s][2], a[s][3], b0, b1);
            }
        }
    }

    float* Cz = C + (size_t)blockIdx.z * 2048 * 128;
    #pragma unroll
    for (int s = 0; s < 2; ++s) {
        int row = m0 + mw + s * 16 + gq;
        #pragma unroll
        for (int j = 0; j < 8; ++j) {
            int col = nw + j * 8 + 2 * qd;
            *(float2*)&Cz[(size_t)row * 128 + col] =
                make_float2(acc[s][j][0], acc[s][j][1]);
            *(float2*)&Cz[(size_t)(row + 8) * 128 + col] =
                make_float2(acc[s][j][2], acc[s][j][3]);
        }
    }
}

// ---------------------------------------------------------------------------
// RoPE + fp16 fragment-quad packers (z=0 -> K, z=1 -> V). 64-kv tiles, 16KB.
// cos/sin from precomputed table (no sincosf in the hot path).
// ---------------------------------------------------------------------------
__global__ void rope_pack(const __half* __restrict__ Kh, const __half* __restrict__ Vh,
                          uint4* __restrict__ Kf, uint4* __restrict__ Vf) {
    __shared__ float S[64][129];
    int g = blockIdx.y, kb = blockIdx.x, z = blockIdx.z, t = threadIdx.x;
    const __half* src = (z ? Vh : Kh) + (size_t)g * 262144 + (size_t)kb * 8192;
    const float2* tab = g_sctab + (size_t)kb * 64 * 64;
    for (int i = t; i < 4096; i += 256) {
        int r = i >> 6, d = i & 63;
        float x1 = __half2float(src[r * 128 + d]);
        float x2 = __half2float(src[r * 128 + d + 64]);
        float2 sc = tab[r * 64 + d];
        S[r][d]      = x1 * sc.x - x2 * sc.y;
        S[r][d + 64] = x1 * sc.y + x2 * sc.x;
    }
    __syncthreads();
    if (z == 0) {
        uint4* dst = Kf + ((size_t)g * 32 + kb) * 1024;
        for (int i = t; i < 1024; i += 256) {
            int ks = i >> 7, jp = (i >> 5) & 3, l = i & 31;
            int gq = l >> 2, qd = l & 3;
            int c0 = jp * 16 + gq, d0 = ks * 16 + 2 * qd;
            dst[i] = make_uint4(
                pack_h2(S[c0][d0],     S[c0][d0 + 1]),
                pack_h2(S[c0][d0 + 8], S[c0][d0 + 9]),
                pack_h2(S[c0 + 8][d0],     S[c0 + 8][d0 + 1]),
                pack_h2(S[c0 + 8][d0 + 8], S[c0 + 8][d0 + 9]));
        }
    } else {
        uint4* dst = Vf + ((size_t)g * 32 + kb) * 1024;
        for (int i = t; i < 1024; i += 256) {
            int ks = i >> 8, jp = (i >> 5) & 7, l = i & 31;
            int gq = l >> 2, qd = l & 3;
            int k0 = ks * 16 + 2 * qd, c0 = jp * 16 + gq;
            dst[i] = make_uint4(
                pack_h2(S[k0][c0],     S[k0 + 1][c0]),
                pack_h2(S[k0 + 8][c0], S[k0 + 9][c0]),
                pack_h2(S[k0][c0 + 8],     S[k0 + 1][c0 + 8]),
                pack_h2(S[k0 + 8][c0 + 8], S[k0 + 9][c0 + 8]));
        }
    }
}

// ---------------------------------------------------------------------------
// Flash attention (R14 config): 128 threads, 4 warps x 16 rows = 64 q-rows,
// kv-tile 64, fp16 mma, no running max, P register-resident, 3 CTAs/SM.
// ---------------------------------------------------------------------------
#define KV0  0          // K (4096 floats) + V (4096 floats) = 32KB
#define KV1  8192
#define ASMF 16384      // floats -> 65536 bytes

__global__ void __launch_bounds__(128, 3) attn_mma(
    const uint4* __restrict__ Qh,     // fp16 [32][2048][128], 16 uint4/row
    const uint4* __restrict__ Kf,     // fp16 frag-quad packed
    const uint4* __restrict__ Vf,
    uint32_t* __restrict__ OcW) {     // fp16 [2048][4096] as u32 words
    extern __shared__ float sm[];
    uint32_t* smU = (uint32_t*)sm;

    const int t = threadIdx.x, lane = t & 31, wid = t >> 5;
    const int gq = lane >> 2, qd = lane & 3;
    const int bid = blockIdx.x;
    const int qb = 31 - (bid >> 5);   // big blocks first
    const int h = bid & 31, g = h & 7;
    const int s0 = qb * 64, m0 = wid * 16;

    // ---- Q (64 rows, fp16, scale pre-folded): raw uint4 copies, 16/row
    const uint4* qsrc = Qh + ((size_t)h * 2048 + s0) * 16;
    for (int i = t; i < 1024; i += 128) {
        int r = i >> 4, w = i & 15;
        *(uint4*)&smU[r * 68 + w * 4] = qsrc[r * 16 + w];
    }
    __syncthreads();
    uint32_t qa[8][4];
    #pragma unroll
    for (int ks = 0; ks < 8; ++ks) {
        qa[ks][0] = smU[(m0 + gq) * 68 + ks * 8 + qd];
        qa[ks][1] = smU[(m0 + gq + 8) * 68 + ks * 8 + qd];
        qa[ks][2] = smU[(m0 + gq) * 68 + ks * 8 + 4 + qd];
        qa[ks][3] = smU[(m0 + gq + 8) * 68 + ks * 8 + 4 + qd];
    }
    __syncthreads();

    float l0 = 0.f, l1 = 0.f;
    float o_acc[16][4];
    #pragma unroll
    for (int j = 0; j < 16; ++j)
        #pragma unroll
        for (int c = 0; c < 4; ++c) o_acc[j][c] = 0.f;

    const int ntiles = qb + 1;
    const float* kbase = (const float*)(Kf + (size_t)g * 32 * 1024);
    const float* vbase = (const float*)(Vf + (size_t)g * 32 * 1024);

    for (int i = t; i < 1024; i += 128) {
        cp16(&sm[KV0 + i * 4], &kbase[i * 4]);
        cp16(&sm[KV0 + 4096 + i * 4], &vbase[i * 4]);
    }
    cp_commit();

    for (int kb = 0; kb < ntiles; ++kb) {
        cp_wait0();
        __syncthreads();
        if (kb + 1 < ntiles) {
            float* b = sm + ((kb & 1) ? KV0 : KV1);
            const float* kg = kbase + (size_t)(kb + 1) * 4096;
            const float* vg = vbase + (size_t)(kb + 1) * 4096;
            for (int i = t; i < 1024; i += 128) {
                cp16(&b[i * 4], &kg[i * 4]);
                cp16(&b[4096 + i * 4], &vg[i * 4]);
            }
            cp_commit();
        }
        const float* cur = sm + ((kb & 1) ? KV1 : KV0);
        const uint4* K4 = (const uint4*)cur;
        const uint4* V4 = (const uint4*)(cur + 4096);

        float s_acc[8][4];
        #pragma unroll
        for (int j = 0; j < 8; ++j)
            #pragma unroll
            for (int c = 0; c < 4; ++c) s_acc[j][c] = 0.f;
        #pragma unroll
        for (int ks = 0; ks < 8; ++ks) {
            #pragma unroll
            for (int jp = 0; jp < 4; ++jp) {
                uint4 b = K4[ks * 128 + jp * 32 + lane];
                mma_f16(s_acc[2 * jp], qa[ks][0], qa[ks][1], qa[ks][2], qa[ks][3],
                        b.x, b.y);
                mma_f16(s_acc[2 * jp + 1], qa[ks][0], qa[ks][1], qa[ks][2], qa[ks][3],
                        b.z, b.w);
            }
        }

        const bool mt = (kb == ntiles - 1);
        const int r0 = s0 + m0 + gq;
        uint32_t pa[8][2];
        #pragma unroll
        for (int j = 0; j < 8; ++j) {
            float p0 = __expf(s_acc[j][0]);
            float p1 = __expf(s_acc[j][1]);
            float p2 = __expf(s_acc[j][2]);
            float p3 = __expf(s_acc[j][3]);
            if (mt) {
                int col = kb * 64 + j * 8 + 2 * qd;
                if (col > r0)         p0 = 0.f;
                if (col + 1 > r0)     p1 = 0.f;
                if (col > r0 + 8)     p2 = 0.f;
                if (col + 1 > r0 + 8) p3 = 0.f;
            }
            l0 += p0 + p1;
            l1 += p2 + p3;
            pa[j][0] = pack_h2(p0, p1);
            pa[j][1] = pack_h2(p2, p3);
        }

        #pragma unroll
        for (int ks = 0; ks < 4; ++ks) {
            uint32_t a0 = pa[2 * ks][0],     a1 = pa[2 * ks][1];
            uint32_t a2 = pa[2 * ks + 1][0], a3 = pa[2 * ks + 1][1];
            #pragma unroll
            for (int jp = 0; jp < 8; ++jp) {
                uint4 v = V4[ks * 256 + jp * 32 + lane];
                mma_f16(o_acc[2 * jp], a0, a1, a2, a3, v.x, v.y);
                mma_f16(o_acc[2 * jp + 1], a0, a1, a2, a3, v.z, v.w);
            }
        }
    }

    l0 += __shfl_xor_sync(0xffffffffu, l0, 1);
    l0 += __shfl_xor_sync(0xffffffffu, l0, 2);
    l1 += __shfl_xor_sync(0xffffffffu, l1, 1);
    l1 += __shfl_xor_sync(0xffffffffu, l1, 2);
    float inv0 = 1.f / l0, inv1 = 1.f / l1;

    __syncthreads();
    #pragma unroll
    for (int j = 0; j < 16; ++j) {
        int w = j * 4 + qd;
        smU[(m0 + gq) * 68 + w]     = pack_h2(o_acc[j][0] * inv0, o_acc[j][1] * inv0);
        smU[(m0 + gq + 8) * 68 + w] = pack_h2(o_acc[j][2] * inv1, o_acc[j][3] * inv1);
    }
    __syncthreads();
    for (int i = t; i < 1024; i += 128) {
        int r = i >> 4, w4 = (i & 15) << 2;
        *(uint4*)&OcW[(size_t)(s0 + r) * 2048 + h * 64 + w4] =
            *(uint4*)&smU[r * 68 + w4];
    }
}

// ---------------------------------------------------------------------------
__global__ void reduce_bias(const float* __restrict__ P, const float* __restrict__ bo,
                            float* __restrict__ out) {
    int i = blockIdx.x * 256 + threadIdx.x;  // 262144 total
    float v = bo[i & 127];
    #pragma unroll
    for (int z = 0; z < 16; ++z) v += P[(size_t)z * 262144 + i];
    out[i] = v;
}

// ---------------------------------------------------------------------------
extern "C" void kernel_launch(void* const* d_in, const int* in_sizes, int n_in,
                              void* d_out, int out_size) {
    const float* query  = (const float*)d_in[0];
    const float* key    = (const float*)d_in[1];
    const float* values = (const float*)d_in[2];
    const float* Wq = (const float*)d_in[4];
    const float* bq = (const float*)d_in[5];
    const float* Wk = (const float*)d_in[6];
    const float* bk = (const float*)d_in[7];
    const float* Wv = (const float*)d_in[8];
    const float* bv = (const float*)d_in[9];
    const float* Wo = (const float*)d_in[10];
    const float* bo = (const float*)d_in[11];
    float* out = (float*)d_out;

    float* buf = nullptr;
    cudaGetSymbolAddress((void**)&buf, g_buf);
    uint32_t* Qh  = (uint32_t*)(buf + OFF_QH);
    uint32_t* Kh  = (uint32_t*)(buf + OFF_KH);
    uint32_t* Vh  = (uint32_t*)(buf + OFF_VH);
    uint4*    Kf  = (uint4*)(buf + OFF_KF);
    uint4*    Vf  = (uint4*)(buf + OFF_VF);
    uint32_t* Oc  = (uint32_t*)(buf + OFF_OC);
    uint32_t* Woh = (uint32_t*)(buf + OFF_WOH);
    float*    Part = buf + OFF_PART;

    init_invfreq<<<1, 64>>>();
    init_sincos<<<512, 256>>>();
    wo_convert<<<1024, 256>>>(Wo, Woh);

    cudaFuncSetAttribute(gemm_qkv, cudaFuncAttributeMaxDynamicSharedMemorySize,
                         2 * 128 * 68 * 4);
    gemm_qkv<<<dim3(48, 16), 256, 2 * 128 * 68 * 4>>>(
        query, key, values, Wq, bq, Wk, bk, Wv, bv, Qh, Kh, Vh);

    rope_pack<<<dim3(32, 8, 2), 256>>>((const __half*)Kh, (const __half*)Vh, Kf, Vf);

    cudaFuncSetAttribute(attn_mma, cudaFuncAttributeMaxDynamicSharedMemorySize,
                         ASMF * 4);
    attn_mma<<<1024, 128, ASMF * 4>>>((const uint4*)Qh, Kf, Vf, Oc);

    gemm_out<<<dim3(1, 16, 16), 256>>>(Oc, Woh, Part, 256);
    reduce_bias<<<1024, 256>>>(Part, bo, out);
}